// round 2
// baseline (speedup 1.0000x reference)
#include <cuda_runtime.h>
#include <math.h>

// Problem constants
#define NPOS   65536      // 8*8*32*32 positions
#define IDIM_  256
#define H_     8
#define DH_    64
#define HD_    512        // H*DH
#define ODIM_  256
#define TM     32         // positions per CTA
#define NT     256        // threads per CTA
#define QST    33         // padded stride for [512][33] column-major tiles
#define SCT    65         // padded stride for scores [32][65]
#define EPS_   1e-5f
#define SCALE_ 0.088388347648318447f   // 1/sqrt(128)

struct Smem {
    float Xs[TM][IDIM_];     // input tile, row-major        (32 KB)
    float qsT[HD_][QST];     // q / (later) v tile, c-major  (66 KB)
    float ksT[HD_][QST];     // k / (later) attn tile        (66 KB)
    float sc[TM][SCT];       // scores / probs [p][h*8+h']   (8.3 KB)
    float cds[TM][2];        // coords per position
};

// ---------------------------------------------------------------------------
// GEMM: dstT[c][p] = sum_k Xs[p][k] * W[k][c],  M=32, N=512, K=256.
// Thread (rg = tid>>5, cg = tid&31) computes rows rg*4..+3, cols cg*4+q+128*j2.
// W streamed from L2 with 1-iteration register prefetch.
// ---------------------------------------------------------------------------
__device__ __forceinline__ void gemm_proj(const float* __restrict__ W,
                                          const Smem& S, float (*dstT)[QST],
                                          int tid)
{
    const int rg = tid >> 5, cg = tid & 31;
    float acc[4][16];
#pragma unroll
    for (int r = 0; r < 4; r++)
#pragma unroll
        for (int c = 0; c < 16; c++) acc[r][c] = 0.f;

    const float* Wb = W + cg * 4;
    float4 wc[4];
    float  xc[4];
#pragma unroll
    for (int j2 = 0; j2 < 4; j2++)
        wc[j2] = *reinterpret_cast<const float4*>(Wb + 128 * j2);
#pragma unroll
    for (int rr = 0; rr < 4; rr++) xc[rr] = S.Xs[rg * 4 + rr][0];

#pragma unroll 2
    for (int k = 0; k < IDIM_; k++) {
        float4 wn[4];
        float  xn[4];
        const int kn = (k + 1 < IDIM_) ? (k + 1) : k;
#pragma unroll
        for (int j2 = 0; j2 < 4; j2++)
            wn[j2] = *reinterpret_cast<const float4*>(Wb + kn * HD_ + 128 * j2);
#pragma unroll
        for (int rr = 0; rr < 4; rr++) xn[rr] = S.Xs[rg * 4 + rr][kn];

#pragma unroll
        for (int rr = 0; rr < 4; rr++) {
            const float x = xc[rr];
#pragma unroll
            for (int j2 = 0; j2 < 4; j2++) {
                acc[rr][j2 * 4 + 0] += x * wc[j2].x;
                acc[rr][j2 * 4 + 1] += x * wc[j2].y;
                acc[rr][j2 * 4 + 2] += x * wc[j2].z;
                acc[rr][j2 * 4 + 3] += x * wc[j2].w;
            }
        }
#pragma unroll
        for (int j2 = 0; j2 < 4; j2++) wc[j2] = wn[j2];
#pragma unroll
        for (int rr = 0; rr < 4; rr++) xc[rr] = xn[rr];
    }

    // store column-major (4-way conflict on scalar STS, negligible volume)
#pragma unroll
    for (int rr = 0; rr < 4; rr++)
#pragma unroll
        for (int j2 = 0; j2 < 4; j2++)
#pragma unroll
            for (int q = 0; q < 4; q++)
                dstT[cg * 4 + q + 128 * j2][rg * 4 + rr] = acc[rr][j2 * 4 + q];
}

// ---------------------------------------------------------------------------
// Per-(position p, head h): bias add + LayerNorm(64) + coordinate rotation.
// Reads/writes column h*64..h*64+63 of T at lane p (conflict-free: lanes = p).
// ---------------------------------------------------------------------------
__device__ __forceinline__ void ln_rotate(float (*T)[QST],
                                          const float* __restrict__ bias,
                                          const float* __restrict__ g,
                                          const float* __restrict__ b,
                                          float coord, int p, int h)
{
    float v[DH_];
    float mu = 0.f;
#pragma unroll
    for (int j = 0; j < DH_; j++) {
        v[j] = T[h * DH_ + j][p] + bias[j];
        mu += v[j];
    }
    mu *= (1.f / DH_);
    float var = 0.f;
#pragma unroll
    for (int j = 0; j < DH_; j++) {
        const float d = v[j] - mu;
        var += d * d;
    }
    const float rs = rsqrtf(var * (1.f / DH_) + EPS_);
#pragma unroll
    for (int j = 0; j < DH_; j++) v[j] = (v[j] - mu) * rs * g[j] + b[j];

#pragma unroll
    for (int j = 0; j < DH_ / 2; j++) {
        float s, c;
        sincosf(coord * (float)j, &s, &c);
        const float f  = v[j];
        const float gg = v[j + DH_ / 2];
        T[h * DH_ + j][p]            = c + (c * f - s * gg);
        T[h * DH_ + DH_ / 2 + j][p]  = s + (s * f + c * gg);
    }
}

// ---------------------------------------------------------------------------
// Fused kernel: projections + LN + rotation + 8x8 attention + output GEMM
// ---------------------------------------------------------------------------
__global__ void __launch_bounds__(NT, 1)
semattn_fused_kernel(const float* __restrict__ nodal,
                     const float* __restrict__ coords,
                     const float* __restrict__ WQ,
                     const float* __restrict__ WK,
                     const float* __restrict__ WV,
                     const float* __restrict__ biasQ,
                     const float* __restrict__ biasK,
                     const float* __restrict__ lnQg,
                     const float* __restrict__ lnQb,
                     const float* __restrict__ lnKg,
                     const float* __restrict__ lnKb,
                     const float* __restrict__ Wout,
                     const float* __restrict__ bout,
                     float* __restrict__ out)
{
    extern __shared__ float smem_f[];
    Smem& S = *reinterpret_cast<Smem*>(smem_f);
    const int  tid  = threadIdx.x;
    const long pos0 = (long)blockIdx.x * TM;

    // ---- load X tile, coords; zero scores ----
    {
        const float4* xin = reinterpret_cast<const float4*>(nodal + pos0 * IDIM_);
        float4* xs = reinterpret_cast<float4*>(&S.Xs[0][0]);
#pragma unroll
        for (int i = 0; i < (TM * IDIM_ / 4) / NT; i++)
            xs[tid + i * NT] = xin[tid + i * NT];
        if (tid < TM * 2)
            (&S.cds[0][0])[tid] = coords[pos0 * 2 + tid];
        for (int i = tid; i < TM * SCT; i += NT)
            (&S.sc[0][0])[i] = 0.f;
    }
    __syncthreads();

    const int h = tid >> 5;   // head (warp id)
    const int p = tid & 31;   // position within tile (lane)
    const int rg = tid >> 5, cg = tid & 31;

    // ================= Phase A: Q/K projections, LN+rotate, scores ==========
#pragma unroll
    for (int n = 0; n < 2; n++) {
        gemm_proj(WQ + n * IDIM_ * HD_, S, S.qsT, tid);
        gemm_proj(WK + n * IDIM_ * HD_, S, S.ksT, tid);
        __syncthreads();
        {
            const float cd = S.cds[p][n];
            ln_rotate(S.qsT, biasQ + (n * H_ + h) * DH_, lnQg + n * DH_,
                      lnQb + n * DH_, cd, p, h);
            ln_rotate(S.ksT, biasK + (n * H_ + h) * DH_, lnKg + n * DH_,
                      lnKb + n * DH_, cd, p, h);
        }
        __syncthreads();
        {   // scores[p][h][h'] += q_n[p,h,:] . k_n[p,h',:]
            float qreg[DH_];
#pragma unroll
            for (int j = 0; j < DH_; j++) qreg[j] = S.qsT[h * DH_ + j][p];
#pragma unroll
            for (int h2 = 0; h2 < H_; h2++) {
                float a = 0.f;
#pragma unroll
                for (int j = 0; j < DH_; j++)
                    a += qreg[j] * S.ksT[h2 * DH_ + j][p];
                S.sc[p][h * H_ + h2] += a;
            }
        }
        __syncthreads();
    }

    // ================= softmax over h' (one row per thread) =================
    {
        float r[H_];
        float mx = -1e30f;
#pragma unroll
        for (int j = 0; j < H_; j++) {
            r[j] = S.sc[p][h * H_ + j] * SCALE_;
            mx = fmaxf(mx, r[j]);
        }
        float sum = 0.f;
#pragma unroll
        for (int j = 0; j < H_; j++) {
            r[j] = expf(r[j] - mx);
            sum += r[j];
        }
        const float inv = 1.f / sum;
#pragma unroll
        for (int j = 0; j < H_; j++) S.sc[p][h * H_ + j] = r[j] * inv;
    }
    __syncthreads();

    // ================= Phase B: V projection, attn mix, output GEMM =========
    float oacc[4][8];
#pragma unroll
    for (int rr = 0; rr < 4; rr++)
#pragma unroll
        for (int c = 0; c < 8; c++) oacc[rr][c] = 0.f;

#pragma unroll
    for (int n = 0; n < 2; n++) {
        gemm_proj(WV + n * IDIM_ * HD_, S, S.qsT, tid);   // vsT in qsT
        __syncthreads();
        {   // attnT[h*64+j][p] = sum_h' P[p][h][h'] * v[p][h'][j]
            float pr[H_];
#pragma unroll
            for (int h2 = 0; h2 < H_; h2++) pr[h2] = S.sc[p][h * H_ + h2];
#pragma unroll
            for (int j = 0; j < DH_; j++) {
                float a = 0.f;
#pragma unroll
                for (int h2 = 0; h2 < H_; h2++)
                    a += pr[h2] * S.qsT[h2 * DH_ + j][p];
                S.ksT[h * DH_ + j][p] = a;                // attnT in ksT
            }
        }
        __syncthreads();
        {   // out[p][:] += attn_n[p][:] @ Wout[rows for this n]
            const float* Wb = Wout + cg * 4;
            int r0 = n * DH_;                             // row for k=0
            float4 w0 = *reinterpret_cast<const float4*>(Wb + r0 * ODIM_);
            float4 w1 = *reinterpret_cast<const float4*>(Wb + r0 * ODIM_ + 128);
            float  ac[4];
#pragma unroll
            for (int rr = 0; rr < 4; rr++) ac[rr] = S.ksT[0][rg * 4 + rr];

#pragma unroll 2
            for (int k = 0; k < HD_; k++) {
                float4 w0n, w1n;
                float  an[4];
                const int kn = (k + 1 < HD_) ? (k + 1) : k;
                const int rn = ((kn >> 6) << 7) + n * DH_ + (kn & 63);
                w0n = *reinterpret_cast<const float4*>(Wb + rn * ODIM_);
                w1n = *reinterpret_cast<const float4*>(Wb + rn * ODIM_ + 128);
#pragma unroll
                for (int rr = 0; rr < 4; rr++) an[rr] = S.ksT[kn][rg * 4 + rr];

#pragma unroll
                for (int rr = 0; rr < 4; rr++) {
                    const float a = ac[rr];
                    oacc[rr][0] += a * w0.x; oacc[rr][1] += a * w0.y;
                    oacc[rr][2] += a * w0.z; oacc[rr][3] += a * w0.w;
                    oacc[rr][4] += a * w1.x; oacc[rr][5] += a * w1.y;
                    oacc[rr][6] += a * w1.z; oacc[rr][7] += a * w1.w;
                }
                w0 = w0n; w1 = w1n;
#pragma unroll
                for (int rr = 0; rr < 4; rr++) ac[rr] = an[rr];
            }
        }
        __syncthreads();
    }

    // ================= epilogue: + bout, coalesced float4 store =============
#pragma unroll
    for (int rr = 0; rr < 4; rr++) {
        const long row = pos0 + rg * 4 + rr;
#pragma unroll
        for (int j2 = 0; j2 < 2; j2++) {
            const int c0 = cg * 4 + 128 * j2;
            float4 o;
            o.x = oacc[rr][j2 * 4 + 0] + bout[c0 + 0];
            o.y = oacc[rr][j2 * 4 + 1] + bout[c0 + 1];
            o.z = oacc[rr][j2 * 4 + 2] + bout[c0 + 2];
            o.w = oacc[rr][j2 * 4 + 3] + bout[c0 + 3];
            *reinterpret_cast<float4*>(out + row * ODIM_ + c0) = o;
        }
    }
}

// ---------------------------------------------------------------------------
extern "C" void kernel_launch(void* const* d_in, const int* in_sizes, int n_in,
                              void* d_out, int out_size)
{
    const float* nodal  = (const float*)d_in[0];
    const float* coords = (const float*)d_in[1];
    const float* WQ     = (const float*)d_in[2];
    const float* WK     = (const float*)d_in[3];
    const float* WV     = (const float*)d_in[4];
    const float* biasQ  = (const float*)d_in[5];
    const float* biasK  = (const float*)d_in[6];
    const float* lnQg   = (const float*)d_in[7];
    const float* lnQb   = (const float*)d_in[8];
    const float* lnKg   = (const float*)d_in[9];
    const float* lnKb   = (const float*)d_in[10];
    const float* Wout   = (const float*)d_in[11];
    const float* bout   = (const float*)d_in[12];
    float* out = (float*)d_out;

    const int smem_bytes = (int)sizeof(Smem);
    cudaFuncSetAttribute(semattn_fused_kernel,
                         cudaFuncAttributeMaxDynamicSharedMemorySize, smem_bytes);

    semattn_fused_kernel<<<NPOS / TM, NT, smem_bytes>>>(
        nodal, coords, WQ, WK, WV, biasQ, biasK,
        lnQg, lnQb, lnKg, lnKb, Wout, bout, out);
}

// round 7
// speedup vs baseline: 3.5257x; 3.5257x over previous
#include <cuda_runtime.h>
#include <cuda_fp16.h>
#include <cstdint>
#include <math.h>

#define EPS_   1e-5f
#define SCALE_ 0.088388347648318447f   // 1/sqrt(128)

// ---------------- static scratch ----------------
__device__ __half g_WT [3072 * 256];    // [c][k]  (QKV cat), fp16
__device__ __half g_WoT[256 * 1024];    // [c][k]  Wout^T, fp16
__device__ __half g_Ch [65536UL * 3072];// [pos][c] raw qkv, fp16
__device__ __half g_A2 [65536UL * 1024];// [pos][k] attn output, fp16

// ---------------- helpers ----------------
__device__ __forceinline__ uint32_t smem_u32(const void* p) {
    uint32_t a;
    asm("{ .reg .u64 t; cvta.to.shared.u64 t, %1; cvt.u32.u64 %0, t; }" : "=r"(a) : "l"(p));
    return a;
}

#define LDM_X4(r0, r1, r2, r3, ad) \
    asm volatile("ldmatrix.sync.aligned.m8n8.x4.shared.b16 {%0,%1,%2,%3}, [%4];" \
                 : "=r"(r0), "=r"(r1), "=r"(r2), "=r"(r3) : "r"(ad))
#define LDM_X2(r0, r1, ad) \
    asm volatile("ldmatrix.sync.aligned.m8n8.x2.shared.b16 {%0,%1}, [%2];" \
                 : "=r"(r0), "=r"(r1) : "r"(ad))
#define MMA16816(d, a, b) \
    asm volatile("mma.sync.aligned.m16n8k16.row.col.f32.f16.f16.f32 " \
                 "{%0,%1,%2,%3}, {%4,%5,%6,%7}, {%8,%9}, {%0,%1,%2,%3};" \
                 : "+f"((d)[0]), "+f"((d)[1]), "+f"((d)[2]), "+f"((d)[3]) \
                 : "r"((a)[0]), "r"((a)[1]), "r"((a)[2]), "r"((a)[3]), \
                   "r"((b)[0]), "r"((b)[1]))

// ============================ K0: weight prep ============================
__global__ void k0_prep(const float* __restrict__ WQ, const float* __restrict__ WK,
                        const float* __restrict__ WV, const float* __restrict__ Wout)
{
    const int i = blockIdx.x * 256 + threadIdx.x;
    if (i < 3072 * 256) {
        const int c = i >> 8, k = i & 255;
        const int t = c >> 10, r = c & 1023, n = r >> 9, cc = r & 511;
        const float* W = (t == 0) ? WQ : (t == 1) ? WK : WV;
        g_WT[i] = __float2half_rn(W[((size_t)n * 256 + k) * 512 + cc]);
    } else {
        const int j = i - 3072 * 256;
        if (j < 256 * 1024) {
            const int c = j >> 10, k = j & 1023;
            g_WoT[j] = __float2half_rn(Wout[(size_t)k * 256 + c]);
        }
    }
}

// ============================ K1: projection GEMM ============================
// C[pos][c] = X[pos][k] * WT[c][k]^T.  CTA = 128 pos, loops 24 chunks of 128 c.
#define XP 264                    // smem pitch (halves), 528B rows -> conflict-free ldmatrix
#define K1_XS  0
#define K1_WS  67584
#define K1_STG 135168             // half2 [128][68]
#define K1_SMEM 169984

__global__ void __launch_bounds__(256, 1)
k1_proj(const float* __restrict__ nodal)
{
    extern __shared__ __align__(16) char sm[];
    __half* Xs = (__half*)(sm + K1_XS);
    __half* Ws = (__half*)(sm + K1_WS);
    half2*  stg = (half2*)(sm + K1_STG);     // [128][68]
    const uint32_t sb = smem_u32(sm);

    const int tid = threadIdx.x, wid = tid >> 5, lane = tid & 31;
    const int wm = wid >> 2, wn = wid & 3;   // warp tile: rows wm*64, cols wn*32
    const size_t pos0 = (size_t)blockIdx.x * 128;

    // load X tile -> fp16 smem
    {
        const int r = tid >> 1, seg = tid & 1;
        const float4* src = reinterpret_cast<const float4*>(nodal + (pos0 + r) * 256 + seg * 128);
        half2* drow = reinterpret_cast<half2*>(Xs + r * XP + seg * 128);
#pragma unroll
        for (int i = 0; i < 32; i++) {
            float4 v = src[i];
            drow[i * 2]     = __floats2half2_rn(v.x, v.y);
            drow[i * 2 + 1] = __floats2half2_rn(v.z, v.w);
        }
    }

    bool havePrev = false;
    int  prevC = 0;
    for (int c = 0; c < 24; c++) {
        __syncthreads();
        // store previous chunk's staged output
        if (havePrev) {
            const int r = tid >> 1, seg = tid & 1;
            const uint4* s4 = reinterpret_cast<const uint4*>(&stg[r * 68 + seg * 32]);
            uint4* d4 = reinterpret_cast<uint4*>(g_Ch + (pos0 + r) * 3072 + prevC * 128 + seg * 64);
#pragma unroll
            for (int i = 0; i < 8; i++) d4[i] = s4[i];
        }
        // load W chunk
        {
            const int r = tid >> 1, seg = tid & 1;
            const uint4* s4 = reinterpret_cast<const uint4*>(g_WT + ((size_t)c * 128 + r) * 256 + seg * 128);
            uint4* d4 = reinterpret_cast<uint4*>(Ws + r * XP + seg * 128);
#pragma unroll
            for (int i = 0; i < 16; i++) d4[i] = s4[i];
        }
        __syncthreads();

        float acc[4][4][4];
#pragma unroll
        for (int mt = 0; mt < 4; mt++)
#pragma unroll
            for (int nt = 0; nt < 4; nt++)
#pragma unroll
                for (int q = 0; q < 4; q++) acc[mt][nt][q] = 0.f;

#pragma unroll
        for (int k0 = 0; k0 < 256; k0 += 16) {
            uint32_t a[4][4], b[4][2];
#pragma unroll
            for (int mt = 0; mt < 4; mt++) {
                const uint32_t ad = sb + K1_XS +
                    (((wm * 64 + mt * 16 + (lane & 15)) * XP + k0 + ((lane >> 4) << 3)) << 1);
                LDM_X4(a[mt][0], a[mt][1], a[mt][2], a[mt][3], ad);
            }
#pragma unroll
            for (int nt = 0; nt < 4; nt++) {
                const uint32_t bd = sb + K1_WS +
                    (((wn * 32 + nt * 8 + (lane & 7)) * XP + k0 + (((lane >> 3) & 1) << 3)) << 1);
                LDM_X2(b[nt][0], b[nt][1], bd);
            }
#pragma unroll
            for (int mt = 0; mt < 4; mt++)
#pragma unroll
                for (int nt = 0; nt < 4; nt++)
                    MMA16816(acc[mt][nt], a[mt], b[nt]);
        }

        // stage accumulators as fp16
        {
            const int g = lane >> 2, t4 = lane & 3;
#pragma unroll
            for (int mt = 0; mt < 4; mt++)
#pragma unroll
                for (int nt = 0; nt < 4; nt++) {
                    const int row = wm * 64 + mt * 16 + g;
                    const int col = wn * 32 + nt * 8 + t4 * 2;
                    stg[row * 68 + (col >> 1)]       = __floats2half2_rn(acc[mt][nt][0], acc[mt][nt][1]);
                    stg[(row + 8) * 68 + (col >> 1)] = __floats2half2_rn(acc[mt][nt][2], acc[mt][nt][3]);
                }
        }
        havePrev = true;
        prevC = c;
    }
    __syncthreads();
    {
        const int r = tid >> 1, seg = tid & 1;
        const uint4* s4 = reinterpret_cast<const uint4*>(&stg[r * 68 + seg * 32]);
        uint4* d4 = reinterpret_cast<uint4*>(g_Ch + (pos0 + r) * 3072 + 23 * 128 + seg * 64);
#pragma unroll
        for (int i = 0; i < 8; i++) d4[i] = s4[i];
    }
}

// ============================ K2: pointwise ============================
// CTA = 32 positions; warp = head, lane = position.
__device__ __forceinline__ void load64(float* dst, const __half* src)
{
    const uint4* s4 = reinterpret_cast<const uint4*>(src);
#pragma unroll
    for (int u = 0; u < 8; u++) {
        uint4 v = s4[u];
        float2 f0 = __half22float2(*reinterpret_cast<half2*>(&v.x));
        float2 f1 = __half22float2(*reinterpret_cast<half2*>(&v.y));
        float2 f2 = __half22float2(*reinterpret_cast<half2*>(&v.z));
        float2 f3 = __half22float2(*reinterpret_cast<half2*>(&v.w));
        dst[u * 8 + 0] = f0.x; dst[u * 8 + 1] = f0.y;
        dst[u * 8 + 2] = f1.x; dst[u * 8 + 3] = f1.y;
        dst[u * 8 + 4] = f2.x; dst[u * 8 + 5] = f2.y;
        dst[u * 8 + 6] = f3.x; dst[u * 8 + 7] = f3.y;
    }
}

__device__ __forceinline__ void lnrot_t(float* x, const float* __restrict__ bias,
                                        const float* __restrict__ g,
                                        const float* __restrict__ b,
                                        const float* __restrict__ ct,
                                        const float* __restrict__ st, int p)
{
    float mu = 0.f;
#pragma unroll
    for (int j = 0; j < 64; j++) { x[j] += bias[j]; mu += x[j]; }
    mu *= (1.f / 64.f);
    float var = 0.f;
#pragma unroll
    for (int j = 0; j < 64; j++) { const float d = x[j] - mu; var += d * d; }
    const float rs = rsqrtf(var * (1.f / 64.f) + EPS_);
    float v[64];
#pragma unroll
    for (int j = 0; j < 64; j++) v[j] = (x[j] - mu) * rs * g[j] + b[j];
#pragma unroll
    for (int j = 0; j < 32; j++) {
        const float c = ct[j * 32 + p], s = st[j * 32 + p];
        const float f = v[j], gg = v[j + 32];
        x[j]      = c + (c * f - s * gg);
        x[j + 32] = s + (s * f + c * gg);
    }
}

__global__ void __launch_bounds__(256, 1)
k2_attn(const float* __restrict__ coords,
        const float* __restrict__ biasQ, const float* __restrict__ biasK,
        const float* __restrict__ lnQg, const float* __restrict__ lnQb,
        const float* __restrict__ lnKg, const float* __restrict__ lnKb)
{
    extern __shared__ __align__(16) float sf[];
    float* buf0 = sf;                      // [512][33]
    float* ctab = sf + 512 * 33;           // [2][32 j][32 p]
    float* stab = ctab + 2048;             // [2][32 j][32 p]
    const int tid = threadIdx.x, h = tid >> 5, p = tid & 31;
    const size_t pos0 = (size_t)blockIdx.x * 32;
    const size_t gpos = pos0 + p;
    const __half* Cb = g_Ch + gpos * 3072;

    // sincos tables: 2048 entries, 8 per thread
    for (int idx = tid; idx < 2048; idx += 256) {
        const int n = idx >> 10, j = (idx >> 5) & 31, pp = idx & 31;
        const float cd = coords[(pos0 + pp) * 2 + n];
        float s, c;
        sincosf(cd * (float)j, &s, &c);
        ctab[idx] = c;
        stab[idx] = s;
    }
    __syncthreads();

    float acc[8];
#pragma unroll
    for (int i = 0; i < 8; i++) acc[i] = 0.f;

#pragma unroll
    for (int n = 0; n < 2; n++) {
        const float* ct = ctab + n * 1024;
        const float* st = stab + n * 1024;
        float kx[64];
        load64(kx, Cb + 1024 + n * 512 + h * 64);
        lnrot_t(kx, biasK + (n * 8 + h) * 64, lnKg + n * 64, lnKb + n * 64, ct, st, p);
        __syncthreads();
#pragma unroll
        for (int j = 0; j < 64; j++) buf0[(h * 64 + j) * 33 + p] = kx[j];
        float qe[64];
        load64(qe, Cb + n * 512 + h * 64);
        lnrot_t(qe, biasQ + (n * 8 + h) * 64, lnQg + n * 64, lnQb + n * 64, ct, st, p);
        __syncthreads();
#pragma unroll
        for (int h2 = 0; h2 < 8; h2++) {
            float a = 0.f;
#pragma unroll
            for (int j = 0; j < 64; j++) a += qe[j] * buf0[(h2 * 64 + j) * 33 + p];
            acc[h2] += a;
        }
    }
    // softmax over 8
    float pr[8], mx = -1e30f, sum = 0.f;
#pragma unroll
    for (int i = 0; i < 8; i++) { acc[i] *= SCALE_; mx = fmaxf(mx, acc[i]); }
#pragma unroll
    for (int i = 0; i < 8; i++) { pr[i] = expf(acc[i] - mx); sum += pr[i]; }
    const float inv = 1.f / sum;
#pragma unroll
    for (int i = 0; i < 8; i++) pr[i] *= inv;

#pragma unroll
    for (int n = 0; n < 2; n++) {
        float vx[64];
        load64(vx, Cb + 2048 + n * 512 + h * 64);
        __syncthreads();
#pragma unroll
        for (int j = 0; j < 64; j++) buf0[(h * 64 + j) * 33 + p] = vx[j];
        __syncthreads();
        float av[64];
#pragma unroll
        for (int j = 0; j < 64; j++) {
            float a = 0.f;
#pragma unroll
            for (int h2 = 0; h2 < 8; h2++) a += pr[h2] * buf0[(h2 * 64 + j) * 33 + p];
            av[j] = a;
        }
        // write A2[pos][h*128 + n*64 .. +63] fp16
        uint4* d4 = reinterpret_cast<uint4*>(g_A2 + gpos * 1024 + h * 128 + n * 64);
#pragma unroll
        for (int u = 0; u < 8; u++) {
            uint4 v;
            half2 h0 = __floats2half2_rn(av[u * 8 + 0], av[u * 8 + 1]);
            half2 h1 = __floats2half2_rn(av[u * 8 + 2], av[u * 8 + 3]);
            half2 h2v = __floats2half2_rn(av[u * 8 + 4], av[u * 8 + 5]);
            half2 h3 = __floats2half2_rn(av[u * 8 + 6], av[u * 8 + 7]);
            v.x = *reinterpret_cast<uint32_t*>(&h0);
            v.y = *reinterpret_cast<uint32_t*>(&h1);
            v.z = *reinterpret_cast<uint32_t*>(&h2v);
            v.w = *reinterpret_cast<uint32_t*>(&h3);
            d4[u] = v;
        }
    }
}

// ============================ K3: output GEMM ============================
// out[pos][256] = A2[pos][1024] * WoT[c][1024]^T + bout.  CTA 128 pos x 128 c.
#define K3P 136
#define K3_AS 0
#define K3_BS 34816
#define K3_SMEM 69632

__global__ void __launch_bounds__(256, 1)
k3_out(const float* __restrict__ bout, float* __restrict__ out)
{
    extern __shared__ __align__(16) char sm[];
    __half* As = (__half*)(sm + K3_AS);
    __half* Bs = (__half*)(sm + K3_BS);
    float*  stage = (float*)sm;              // [128][132], reused after mma
    const uint32_t sb = smem_u32(sm);

    const int tid = threadIdx.x, wid = tid >> 5, lane = tid & 31;
    const int wm = wid >> 1, wn = wid & 1;   // warp tile: rows wm*32, cols wn*64
    const size_t pos0 = (size_t)(blockIdx.x >> 1) * 128;
    const int c0 = (blockIdx.x & 1) * 128;

    float acc[2][8][4];
#pragma unroll
    for (int mt = 0; mt < 2; mt++)
#pragma unroll
        for (int nt = 0; nt < 8; nt++)
#pragma unroll
            for (int q = 0; q < 4; q++) acc[mt][nt][q] = 0.f;

    for (int kc = 0; kc < 8; kc++) {
        __syncthreads();
        {
            const int r = tid >> 1, seg = tid & 1;
            const uint4* sa = reinterpret_cast<const uint4*>(g_A2 + (pos0 + r) * 1024 + kc * 128 + seg * 64);
            uint4* da = reinterpret_cast<uint4*>(As + r * K3P + seg * 64);
            const uint4* sbp = reinterpret_cast<const uint4*>(g_WoT + (size_t)(c0 + r) * 1024 + kc * 128 + seg * 64);
            uint4* db = reinterpret_cast<uint4*>(Bs + r * K3P + seg * 64);
#pragma unroll
            for (int i = 0; i < 8; i++) { da[i] = sa[i]; db[i] = sbp[i]; }
        }
        __syncthreads();

#pragma unroll
        for (int k0 = 0; k0 < 128; k0 += 16) {
            uint32_t a[2][4], b[8][2];
#pragma unroll
            for (int mt = 0; mt < 2; mt++) {
                const uint32_t ad = sb + K3_AS +
                    (((wm * 32 + mt * 16 + (lane & 15)) * K3P + k0 + ((lane >> 4) << 3)) << 1);
                LDM_X4(a[mt][0], a[mt][1], a[mt][2], a[mt][3], ad);
            }
#pragma unroll
            for (int nt = 0; nt < 8; nt++) {
                const uint32_t bd = sb + K3_BS +
                    (((wn * 64 + nt * 8 + (lane & 7)) * K3P + k0 + (((lane >> 3) & 1) << 3)) << 1);
                LDM_X2(b[nt][0], b[nt][1], bd);
            }
#pragma unroll
            for (int mt = 0; mt < 2; mt++)
#pragma unroll
                for (int nt = 0; nt < 8; nt++)
                    MMA16816(acc[mt][nt], a[mt], b[nt]);
        }
    }
    __syncthreads();
    // stage fp32 result
    {
        const int g = lane >> 2, t4 = lane & 3;
#pragma unroll
        for (int mt = 0; mt < 2; mt++)
#pragma unroll
            for (int nt = 0; nt < 8; nt++) {
                const int row = wm * 32 + mt * 16 + g;
                const int col = wn * 64 + nt * 8 + t4 * 2;
                stage[row * 132 + col]           = acc[mt][nt][0];
                stage[row * 132 + col + 1]       = acc[mt][nt][1];
                stage[(row + 8) * 132 + col]     = acc[mt][nt][2];
                stage[(row + 8) * 132 + col + 1] = acc[mt][nt][3];
            }
    }
    __syncthreads();
    {
        const int r = tid >> 1, seg = tid & 1;
        float* drow = out + (pos0 + r) * 256 + c0 + seg * 64;
        const float* srow = stage + r * 132 + seg * 64;
        const float* brow = bout + c0 + seg * 64;
#pragma unroll
        for (int i = 0; i < 16; i++) {
            float4 v = *reinterpret_cast<const float4*>(srow + i * 4);
            float4 bb = *reinterpret_cast<const float4*>(brow + i * 4);
            v.x += bb.x; v.y += bb.y; v.z += bb.z; v.w += bb.w;
            *reinterpret_cast<float4*>(drow + i * 4) = v;
        }
    }
}

// ---------------------------------------------------------------------------
extern "C" void kernel_launch(void* const* d_in, const int* in_sizes, int n_in,
                              void* d_out, int out_size)
{
    const float* nodal  = (const float*)d_in[0];
    const float* coords = (const float*)d_in[1];
    const float* WQ     = (const float*)d_in[2];
    const float* WK     = (const float*)d_in[3];
    const float* WV     = (const float*)d_in[4];
    const float* biasQ  = (const float*)d_in[5];
    const float* biasK  = (const float*)d_in[6];
    const float* lnQg   = (const float*)d_in[7];
    const float* lnQb   = (const float*)d_in[8];
    const float* lnKg   = (const float*)d_in[9];
    const float* lnKb   = (const float*)d_in[10];
    const float* Wout   = (const float*)d_in[11];
    const float* bout   = (const float*)d_in[12];
    float* out = (float*)d_out;

    cudaFuncSetAttribute(k1_proj, cudaFuncAttributeMaxDynamicSharedMemorySize, K1_SMEM);
    cudaFuncSetAttribute(k2_attn, cudaFuncAttributeMaxDynamicSharedMemorySize, 83968);
    cudaFuncSetAttribute(k3_out,  cudaFuncAttributeMaxDynamicSharedMemorySize, K3_SMEM);

    k0_prep<<<4096, 256>>>(WQ, WK, WV, Wout);
    k1_proj<<<512, 256, K1_SMEM>>>(nodal);
    k2_attn<<<2048, 256, 83968>>>(coords, biasQ, biasK, lnQg, lnQb, lnKg, lnKb);
    k3_out<<<1024, 256, K3_SMEM>>>(bout, out);
}

// round 10
// speedup vs baseline: 3.7627x; 1.0672x over previous
#include <cuda_runtime.h>
#include <cuda_fp16.h>
#include <cstdint>
#include <math.h>

#define EPS_   1e-5f
#define SCALE_ 0.088388347648318447f   // 1/sqrt(128)

// ---------------- static scratch ----------------
__device__ __half g_WT [3072 * 256];    // [c][k]  (QKV cat), fp16
__device__ __half g_WoT[256 * 1024];    // [c][k]  Wout^T, fp16
__device__ __half g_Ch [65536UL * 3072];// [pos][c] raw qkv, fp16
__device__ __half g_A2 [65536UL * 1024];// [pos][k] attn output, fp16

// ---------------- helpers ----------------
__device__ __forceinline__ uint32_t smem_u32(const void* p) {
    uint32_t a;
    asm("{ .reg .u64 t; cvta.to.shared.u64 t, %1; cvt.u32.u64 %0, t; }" : "=r"(a) : "l"(p));
    return a;
}

#define LDM_X4(r0, r1, r2, r3, ad) \
    asm volatile("ldmatrix.sync.aligned.m8n8.x4.shared.b16 {%0,%1,%2,%3}, [%4];" \
                 : "=r"(r0), "=r"(r1), "=r"(r2), "=r"(r3) : "r"(ad))
#define LDM_X2(r0, r1, ad) \
    asm volatile("ldmatrix.sync.aligned.m8n8.x2.shared.b16 {%0,%1}, [%2];" \
                 : "=r"(r0), "=r"(r1) : "r"(ad))
#define MMA16816(d, a, b) \
    asm volatile("mma.sync.aligned.m16n8k16.row.col.f32.f16.f16.f32 " \
                 "{%0,%1,%2,%3}, {%4,%5,%6,%7}, {%8,%9}, {%0,%1,%2,%3};" \
                 : "+f"((d)[0]), "+f"((d)[1]), "+f"((d)[2]), "+f"((d)[3]) \
                 : "r"((a)[0]), "r"((a)[1]), "r"((a)[2]), "r"((a)[3]), \
                   "r"((b)[0]), "r"((b)[1]))

// ============================ K0: weight prep ============================
__global__ void k0_prep(const float* __restrict__ WQ, const float* __restrict__ WK,
                        const float* __restrict__ WV, const float* __restrict__ Wout)
{
    const int i = blockIdx.x * 256 + threadIdx.x;
    if (i < 3072 * 256) {
        const int c = i >> 8, k = i & 255;
        const int t = c >> 10, r = c & 1023, n = r >> 9, cc = r & 511;
        const float* W = (t == 0) ? WQ : (t == 1) ? WK : WV;
        g_WT[i] = __float2half_rn(W[((size_t)n * 256 + k) * 512 + cc]);
    } else {
        const int j = i - 3072 * 256;
        if (j < 256 * 1024) {
            const int c = j >> 10, k = j & 1023;
            g_WoT[j] = __float2half_rn(Wout[(size_t)k * 256 + c]);
        }
    }
}

// ============================ K1: projection GEMM ============================
// C[pos][c] = X[pos][k] * WT[c][k]^T.  CTA = 128 pos, 48 chunks of 64 c.
// smem = X(67584) + W/stage(34816) = 102400 -> 2 CTAs/SM.
#define XP 264                    // X/W smem pitch in halves (528B rows)
#define K1_WOFF 67584             // W buffer offset (bytes)
#define K1_SMEM 102400

__global__ void __launch_bounds__(256, 2)
k1_proj(const float* __restrict__ nodal)
{
    extern __shared__ __align__(16) char sm[];
    __half* Xs = (__half*)sm;
    __half* Ws = (__half*)(sm + K1_WOFF);
    const uint32_t sb = smem_u32(sm);

    const int tid = threadIdx.x, wid = tid >> 5, lane = tid & 31;
    const int wm = wid >> 1, wn = wid & 1;   // warp tile: rows wm*32, cols wn*32
    const int r = tid >> 1, seg = tid & 1;   // for 128-row staging I/O
    const int r2 = tid >> 2, seg2 = tid & 3; // for 64-row W loads
    const size_t pos0 = (size_t)blockIdx.x * 128;

    // load X tile -> fp16 smem
    {
        const float4* src = reinterpret_cast<const float4*>(nodal + (pos0 + r) * 256 + seg * 128);
        half2* drow = reinterpret_cast<half2*>(Xs + r * XP + seg * 128);
#pragma unroll
        for (int i = 0; i < 32; i++) {
            float4 v = src[i];
            drow[i * 2]     = __floats2half2_rn(v.x, v.y);
            drow[i * 2 + 1] = __floats2half2_rn(v.z, v.w);
        }
    }

    for (int c = 0; c < 48; c++) {
        __syncthreads();   // staging buffer free from previous iteration
        // load W chunk: 64 rows x 256 k (8 x uint4 per thread)
        {
            const uint4* s4 = reinterpret_cast<const uint4*>(
                g_WT + ((size_t)c * 64 + r2) * 256 + seg2 * 64);
            uint4* d4 = reinterpret_cast<uint4*>(Ws + r2 * XP + seg2 * 64);
#pragma unroll
            for (int i = 0; i < 8; i++) d4[i] = s4[i];
        }
        __syncthreads();

        float acc[2][4][4];
#pragma unroll
        for (int mt = 0; mt < 2; mt++)
#pragma unroll
            for (int nt = 0; nt < 4; nt++)
#pragma unroll
                for (int q = 0; q < 4; q++) acc[mt][nt][q] = 0.f;

#pragma unroll
        for (int k0 = 0; k0 < 256; k0 += 16) {
            uint32_t a[2][4], b[4][2];
#pragma unroll
            for (int mt = 0; mt < 2; mt++) {
                const uint32_t ad = sb +
                    (((wm * 32 + mt * 16 + (lane & 15)) * XP + k0 + ((lane >> 4) << 3)) << 1);
                LDM_X4(a[mt][0], a[mt][1], a[mt][2], a[mt][3], ad);
            }
#pragma unroll
            for (int nt = 0; nt < 4; nt++) {
                const uint32_t bd = sb + K1_WOFF +
                    (((wn * 32 + nt * 8 + (lane & 7)) * XP + k0 + (((lane >> 3) & 1) << 3)) << 1);
                LDM_X2(b[nt][0], b[nt][1], bd);
            }
#pragma unroll
            for (int mt = 0; mt < 2; mt++)
#pragma unroll
                for (int nt = 0; nt < 4; nt++)
                    MMA16816(acc[mt][nt], a[mt], b[nt]);
        }
        __syncthreads();   // all W reads done; buffer becomes staging

        // stage accumulators as fp16 (pitch 68 half2 = 136 halves)
        {
            half2* stg = (half2*)Ws;
            const int g = lane >> 2, t4 = lane & 3;
#pragma unroll
            for (int mt = 0; mt < 2; mt++)
#pragma unroll
                for (int nt = 0; nt < 4; nt++) {
                    const int row = wm * 32 + mt * 16 + g;
                    const int col = wn * 32 + nt * 8 + t4 * 2;
                    stg[row * 68 + (col >> 1)]       = __floats2half2_rn(acc[mt][nt][0], acc[mt][nt][1]);
                    stg[(row + 8) * 68 + (col >> 1)] = __floats2half2_rn(acc[mt][nt][2], acc[mt][nt][3]);
                }
        }
        __syncthreads();

        // coalesced writeback: 4 x uint4 per thread (32 halves)
        {
            const uint4* s4 = reinterpret_cast<const uint4*>(Ws + r * 136 + seg * 32);
            uint4* d4 = reinterpret_cast<uint4*>(g_Ch + (pos0 + r) * 3072 + c * 64 + seg * 32);
#pragma unroll
            for (int i = 0; i < 4; i++) d4[i] = s4[i];
        }
    }
}

// ============================ K2: pointwise ============================
// CTA = 32 positions; warp = head, lane = position.
__device__ __forceinline__ void load64(float* dst, const __half* src)
{
    const uint4* s4 = reinterpret_cast<const uint4*>(src);
#pragma unroll
    for (int u = 0; u < 8; u++) {
        uint4 v = s4[u];
        float2 f0 = __half22float2(*reinterpret_cast<half2*>(&v.x));
        float2 f1 = __half22float2(*reinterpret_cast<half2*>(&v.y));
        float2 f2 = __half22float2(*reinterpret_cast<half2*>(&v.z));
        float2 f3 = __half22float2(*reinterpret_cast<half2*>(&v.w));
        dst[u * 8 + 0] = f0.x; dst[u * 8 + 1] = f0.y;
        dst[u * 8 + 2] = f1.x; dst[u * 8 + 3] = f1.y;
        dst[u * 8 + 4] = f2.x; dst[u * 8 + 5] = f2.y;
        dst[u * 8 + 6] = f3.x; dst[u * 8 + 7] = f3.y;
    }
}

__device__ __forceinline__ void lnrot_t(float* x, const float* __restrict__ bias,
                                        const float* __restrict__ g,
                                        const float* __restrict__ b,
                                        const float* __restrict__ ct,
                                        const float* __restrict__ st, int p)
{
    float mu = 0.f;
#pragma unroll
    for (int j = 0; j < 64; j++) { x[j] += bias[j]; mu += x[j]; }
    mu *= (1.f / 64.f);
    float var = 0.f;
#pragma unroll
    for (int j = 0; j < 64; j++) { const float d = x[j] - mu; var += d * d; }
    const float rs = rsqrtf(var * (1.f / 64.f) + EPS_);
#pragma unroll
    for (int j = 0; j < 64; j++) x[j] = (x[j] - mu) * rs * g[j] + b[j];   // in-place
#pragma unroll
    for (int j = 0; j < 32; j++) {
        const float c = ct[j * 32 + p], s = st[j * 32 + p];
        const float f = x[j], gg = x[j + 32];
        x[j]      = c + (c * f - s * gg);
        x[j + 32] = s + (s * f + c * gg);
    }
}

__global__ void __launch_bounds__(256)
k2_attn(const float* __restrict__ coords,
        const float* __restrict__ biasQ, const float* __restrict__ biasK,
        const float* __restrict__ lnQg, const float* __restrict__ lnQb,
        const float* __restrict__ lnKg, const float* __restrict__ lnKb)
{
    extern __shared__ __align__(16) float sf[];
    float* buf0 = sf;                      // [512][33]
    float* ctab = sf + 512 * 33;           // [2][32 j][32 p]
    float* stab = ctab + 2048;             // [2][32 j][32 p]
    const int tid = threadIdx.x, h = tid >> 5, p = tid & 31;
    const size_t pos0 = (size_t)blockIdx.x * 32;
    const size_t gpos = pos0 + p;
    const __half* Cb = g_Ch + gpos * 3072;

    // sincos tables: 2048 entries, 8 per thread
    for (int idx = tid; idx < 2048; idx += 256) {
        const int n = idx >> 10, j = (idx >> 5) & 31, pp = idx & 31;
        const float cd = coords[(pos0 + pp) * 2 + n];
        float s, c;
        sincosf(cd * (float)j, &s, &c);
        ctab[idx] = c;
        stab[idx] = s;
    }
    __syncthreads();

    float acc[8];
#pragma unroll
    for (int i = 0; i < 8; i++) acc[i] = 0.f;

#pragma unroll
    for (int n = 0; n < 2; n++) {
        const float* ct = ctab + n * 1024;
        const float* st = stab + n * 1024;
        float kx[64];
        load64(kx, Cb + 1024 + n * 512 + h * 64);
        lnrot_t(kx, biasK + (n * 8 + h) * 64, lnKg + n * 64, lnKb + n * 64, ct, st, p);
        __syncthreads();
#pragma unroll
        for (int j = 0; j < 64; j++) buf0[(h * 64 + j) * 33 + p] = kx[j];
        float qe[64];
        load64(qe, Cb + n * 512 + h * 64);
        lnrot_t(qe, biasQ + (n * 8 + h) * 64, lnQg + n * 64, lnQb + n * 64, ct, st, p);
        __syncthreads();
#pragma unroll
        for (int h2 = 0; h2 < 8; h2++) {
            float a = 0.f;
#pragma unroll
            for (int j = 0; j < 64; j++) a += qe[j] * buf0[(h2 * 64 + j) * 33 + p];
            acc[h2] += a;
        }
    }
    // softmax over 8
    float pr[8], mx = -1e30f, sum = 0.f;
#pragma unroll
    for (int i = 0; i < 8; i++) { acc[i] *= SCALE_; mx = fmaxf(mx, acc[i]); }
#pragma unroll
    for (int i = 0; i < 8; i++) { pr[i] = expf(acc[i] - mx); sum += pr[i]; }
    const float inv = 1.f / sum;
#pragma unroll
    for (int i = 0; i < 8; i++) pr[i] *= inv;

#pragma unroll
    for (int n = 0; n < 2; n++) {
        float vx[64];
        load64(vx, Cb + 2048 + n * 512 + h * 64);
        __syncthreads();
#pragma unroll
        for (int j = 0; j < 64; j++) buf0[(h * 64 + j) * 33 + p] = vx[j];
        __syncthreads();
        float av[64];
#pragma unroll
        for (int j = 0; j < 64; j++) {
            float a = 0.f;
#pragma unroll
            for (int h2 = 0; h2 < 8; h2++) a += pr[h2] * buf0[(h2 * 64 + j) * 33 + p];
            av[j] = a;
        }
        uint4* d4 = reinterpret_cast<uint4*>(g_A2 + gpos * 1024 + h * 128 + n * 64);
#pragma unroll
        for (int u = 0; u < 8; u++) {
            uint4 v;
            half2 h0 = __floats2half2_rn(av[u * 8 + 0], av[u * 8 + 1]);
            half2 h1 = __floats2half2_rn(av[u * 8 + 2], av[u * 8 + 3]);
            half2 h2v = __floats2half2_rn(av[u * 8 + 4], av[u * 8 + 5]);
            half2 h3 = __floats2half2_rn(av[u * 8 + 6], av[u * 8 + 7]);
            v.x = *reinterpret_cast<uint32_t*>(&h0);
            v.y = *reinterpret_cast<uint32_t*>(&h1);
            v.z = *reinterpret_cast<uint32_t*>(&h2v);
            v.w = *reinterpret_cast<uint32_t*>(&h3);
            d4[u] = v;
        }
    }
}

// ============================ K3: output GEMM ============================
// out[pos][c] = A2[pos][1024] * WoT[c][1024]^T + bout.
// CTA = 128 pos x 64 c; smem = A(34816) + B(17408) = 52224 -> 2 CTAs/SM.
#define K3P 136
#define K3_BOFF 34816
#define K3_SMEM 52224

__global__ void __launch_bounds__(256, 2)
k3_out(const float* __restrict__ bout, float* __restrict__ out)
{
    extern __shared__ __align__(16) char sm[];
    __half* As = (__half*)sm;
    __half* Bs = (__half*)(sm + K3_BOFF);
    float*  stage = (float*)sm;              // [128][68] fp32, reuses A buffer
    const uint32_t sb = smem_u32(sm);

    const int tid = threadIdx.x, wid = tid >> 5, lane = tid & 31;
    const int wm = wid >> 1, wn = wid & 1;   // warp tile: rows wm*32, cols wn*32
    const int r = tid >> 1, seg = tid & 1;
    const int r2 = tid >> 2, seg2 = tid & 3;
    const size_t pos0 = (size_t)(blockIdx.x >> 2) * 128;
    const int c0 = (blockIdx.x & 3) * 64;

    float acc[2][4][4];
#pragma unroll
    for (int mt = 0; mt < 2; mt++)
#pragma unroll
        for (int nt = 0; nt < 4; nt++)
#pragma unroll
            for (int q = 0; q < 4; q++) acc[mt][nt][q] = 0.f;

    for (int kc = 0; kc < 8; kc++) {
        __syncthreads();
        {   // A chunk: 128 rows x 128 k (8 uint4/thread)
            const uint4* s4 = reinterpret_cast<const uint4*>(
                g_A2 + (pos0 + r) * 1024 + kc * 128 + seg * 64);
            uint4* d4 = reinterpret_cast<uint4*>(As + r * K3P + seg * 64);
#pragma unroll
            for (int i = 0; i < 8; i++) d4[i] = s4[i];
        }
        {   // B chunk: 64 rows x 128 k (4 uint4/thread)
            const uint4* s4 = reinterpret_cast<const uint4*>(
                g_WoT + (size_t)(c0 + r2) * 1024 + kc * 128 + seg2 * 32);
            uint4* d4 = reinterpret_cast<uint4*>(Bs + r2 * K3P + seg2 * 32);
#pragma unroll
            for (int i = 0; i < 4; i++) d4[i] = s4[i];
        }
        __syncthreads();

#pragma unroll
        for (int k0 = 0; k0 < 128; k0 += 16) {
            uint32_t a[2][4], b[4][2];
#pragma unroll
            for (int mt = 0; mt < 2; mt++) {
                const uint32_t ad = sb +
                    (((wm * 32 + mt * 16 + (lane & 15)) * K3P + k0 + ((lane >> 4) << 3)) << 1);
                LDM_X4(a[mt][0], a[mt][1], a[mt][2], a[mt][3], ad);
            }
#pragma unroll
            for (int nt = 0; nt < 4; nt++) {
                const uint32_t bd = sb + K3_BOFF +
                    (((wn * 32 + nt * 8 + (lane & 7)) * K3P + k0 + (((lane >> 3) & 1) << 3)) << 1);
                LDM_X2(b[nt][0], b[nt][1], bd);
            }
#pragma unroll
            for (int mt = 0; mt < 2; mt++)
#pragma unroll
                for (int nt = 0; nt < 4; nt++)
                    MMA16816(acc[mt][nt], a[mt], b[nt]);
        }
    }
    __syncthreads();
    // stage fp32 result (pitch 68 floats) in the A buffer
    {
        const int g = lane >> 2, t4 = lane & 3;
#pragma unroll
        for (int mt = 0; mt < 2; mt++)
#pragma unroll
            for (int nt = 0; nt < 4; nt++) {
                const int row = wm * 32 + mt * 16 + g;
                const int col = wn * 32 + nt * 8 + t4 * 2;
                stage[row * 68 + col]           = acc[mt][nt][0];
                stage[row * 68 + col + 1]       = acc[mt][nt][1];
                stage[(row + 8) * 68 + col]     = acc[mt][nt][2];
                stage[(row + 8) * 68 + col + 1] = acc[mt][nt][3];
            }
    }
    __syncthreads();
    {
        float* drow = out + (pos0 + r) * 256 + c0 + seg * 32;
        const float* srow = stage + r * 68 + seg * 32;
        const float* brow = bout + c0 + seg * 32;
#pragma unroll
        for (int i = 0; i < 8; i++) {
            float4 v = *reinterpret_cast<const float4*>(srow + i * 4);
            float4 bb = *reinterpret_cast<const float4*>(brow + i * 4);
            v.x += bb.x; v.y += bb.y; v.z += bb.z; v.w += bb.w;
            *reinterpret_cast<float4*>(drow + i * 4) = v;
        }
    }
}

// ---------------------------------------------------------------------------
extern "C" void kernel_launch(void* const* d_in, const int* in_sizes, int n_in,
                              void* d_out, int out_size)
{
    const float* nodal  = (const float*)d_in[0];
    const float* coords = (const float*)d_in[1];
    const float* WQ     = (const float*)d_in[2];
    const float* WK     = (const float*)d_in[3];
    const float* WV     = (const float*)d_in[4];
    const float* biasQ  = (const float*)d_in[5];
    const float* biasK  = (const float*)d_in[6];
    const float* lnQg   = (const float*)d_in[7];
    const float* lnQb   = (const float*)d_in[8];
    const float* lnKg   = (const float*)d_in[9];
    const float* lnKb   = (const float*)d_in[10];
    const float* Wout   = (const float*)d_in[11];
    const float* bout   = (const float*)d_in[12];
    float* out = (float*)d_out;

    cudaFuncSetAttribute(k1_proj, cudaFuncAttributeMaxDynamicSharedMemorySize, K1_SMEM);
    cudaFuncSetAttribute(k2_attn, cudaFuncAttributeMaxDynamicSharedMemorySize, 83968);
    cudaFuncSetAttribute(k3_out,  cudaFuncAttributeMaxDynamicSharedMemorySize, K3_SMEM);

    k0_prep<<<4096, 256>>>(WQ, WK, WV, Wout);
    k1_proj<<<512, 256, K1_SMEM>>>(nodal);
    k2_attn<<<2048, 256, 83968>>>(coords, biasQ, biasK, lnQg, lnQb, lnKg, lnKb);
    k3_out<<<2048, 256, K3_SMEM>>>(bout, out);
}

// round 12
// speedup vs baseline: 3.8956x; 1.0353x over previous
#include <cuda_runtime.h>
#include <cuda_fp16.h>
#include <cstdint>
#include <math.h>

#define EPS_   1e-5f
#define SCALE_ 0.088388347648318447f   // 1/sqrt(128)

// ---------------- static scratch ----------------
__device__ __half g_WT [3072 * 256];    // [c][k]  (QKV cat), fp16
__device__ __half g_WoT[256 * 1024];    // [c][k]  Wout^T, fp16
__device__ __half g_Ch [65536UL * 3072];// [pos][c] raw qkv, fp16
__device__ __half g_A2 [65536UL * 1024];// [pos][k] attn output, fp16

// ---------------- helpers ----------------
__device__ __forceinline__ uint32_t smem_u32(const void* p) {
    uint32_t a;
    asm("{ .reg .u64 t; cvta.to.shared.u64 t, %1; cvt.u32.u64 %0, t; }" : "=r"(a) : "l"(p));
    return a;
}

#define LDM_X4(r0, r1, r2, r3, ad) \
    asm volatile("ldmatrix.sync.aligned.m8n8.x4.shared.b16 {%0,%1,%2,%3}, [%4];" \
                 : "=r"(r0), "=r"(r1), "=r"(r2), "=r"(r3) : "r"(ad))
#define MMA16816(d, a0, a1, a2, a3, b0, b1) \
    asm volatile("mma.sync.aligned.m16n8k16.row.col.f32.f16.f16.f32 " \
                 "{%0,%1,%2,%3}, {%4,%5,%6,%7}, {%8,%9}, {%0,%1,%2,%3};" \
                 : "+f"((d)[0]), "+f"((d)[1]), "+f"((d)[2]), "+f"((d)[3]) \
                 : "r"(a0), "r"(a1), "r"(a2), "r"(a3), "r"(b0), "r"(b1))

// ============================ K0: weight prep ============================
__global__ void k0_prep(const float* __restrict__ WQ, const float* __restrict__ WK,
                        const float* __restrict__ WV, const float* __restrict__ Wout)
{
    const int i = blockIdx.x * 256 + threadIdx.x;
    if (i < 3072 * 256) {
        const int c = i >> 8, k = i & 255;
        const int t = c >> 10, r = c & 1023, n = r >> 9, cc = r & 511;
        const float* W = (t == 0) ? WQ : (t == 1) ? WK : WV;
        g_WT[i] = __float2half_rn(W[((size_t)n * 256 + k) * 512 + cc]);
    } else {
        const int j = i - 3072 * 256;
        if (j < 256 * 1024) {
            const int c = j >> 10, k = j & 1023;
            g_WoT[j] = __float2half_rn(Wout[(size_t)k * 256 + c]);
        }
    }
}

// ============================ K1: projection GEMM ============================
// C[pos][c] = X[pos][k] * WT[c][k]^T.  CTA = 128 pos x 128 c (24 chunks).
// K=256 in 2 halves of 128 so W buffer is 34816B; smem 102400 -> occ 2.
// Warp tile 64x32 (mt=4, nt=4); B ldmatrix.x4 covers two k-steps.
#define XP 264                    // X pitch (halves), 528B rows
#define WP 136                    // W / A / B pitch (halves), 272B rows
#define K1_WOFF 67584
#define K1_SMEM 102400

__global__ void __launch_bounds__(256, 2)
k1_proj(const float* __restrict__ nodal)
{
    extern __shared__ __align__(16) char sm[];
    __half* Xs = (__half*)sm;
    __half* Ws = (__half*)(sm + K1_WOFF);
    const uint32_t sb = smem_u32(sm);

    const int tid = threadIdx.x, wid = tid >> 5, lane = tid & 31;
    const int wm = wid >> 2, wn = wid & 3;   // warp: rows wm*64, cols wn*32
    const int r = tid >> 1, seg = tid & 1;
    const size_t pos0 = (size_t)blockIdx.x * 128;

    // load X tile -> fp16 smem
    {
        const float4* src = reinterpret_cast<const float4*>(nodal + (pos0 + r) * 256 + seg * 128);
        half2* drow = reinterpret_cast<half2*>(Xs + r * XP + seg * 128);
#pragma unroll
        for (int i = 0; i < 32; i++) {
            float4 v = src[i];
            drow[i * 2]     = __floats2half2_rn(v.x, v.y);
            drow[i * 2 + 1] = __floats2half2_rn(v.z, v.w);
        }
    }

    for (int c = 0; c < 24; c++) {
        float acc[4][4][4];
#pragma unroll
        for (int mt = 0; mt < 4; mt++)
#pragma unroll
            for (int nt = 0; nt < 4; nt++)
#pragma unroll
                for (int q = 0; q < 4; q++) acc[mt][nt][q] = 0.f;

#pragma unroll
        for (int kc = 0; kc < 2; kc++) {
            __syncthreads();   // W/stage buffer free
            {   // load W: 128 rows x 128 k -> 64 halves = 8 uint4 per thread
                const uint4* s4 = reinterpret_cast<const uint4*>(
                    g_WT + ((size_t)c * 128 + r) * 256 + kc * 128 + seg * 64);
                uint4* d4 = reinterpret_cast<uint4*>(Ws + r * WP + seg * 64);
#pragma unroll
                for (int i = 0; i < 8; i++) d4[i] = s4[i];
            }
            __syncthreads();

#pragma unroll
            for (int k0 = 0; k0 < 128; k0 += 32) {
                uint32_t b[4][4];
#pragma unroll
                for (int nt = 0; nt < 4; nt++) {
                    const uint32_t bd = sb + K1_WOFF +
                        (((wn * 32 + nt * 8 + (lane & 7)) * WP + k0 + ((lane >> 3) << 3)) << 1);
                    LDM_X4(b[nt][0], b[nt][1], b[nt][2], b[nt][3], bd);
                }
#pragma unroll
                for (int half = 0; half < 2; half++) {
                    uint32_t a[4][4];
#pragma unroll
                    for (int mt = 0; mt < 4; mt++) {
                        const uint32_t ad = sb +
                            (((wm * 64 + mt * 16 + (lane & 15)) * XP
                              + kc * 128 + k0 + half * 16 + ((lane >> 4) << 3)) << 1);
                        LDM_X4(a[mt][0], a[mt][1], a[mt][2], a[mt][3], ad);
                    }
#pragma unroll
                    for (int mt = 0; mt < 4; mt++)
#pragma unroll
                        for (int nt = 0; nt < 4; nt++)
                            MMA16816(acc[mt][nt], a[mt][0], a[mt][1], a[mt][2], a[mt][3],
                                     b[nt][half * 2], b[nt][half * 2 + 1]);
                }
            }
        }
        __syncthreads();   // all W reads done; buffer becomes staging

        // stage accumulators as fp16 (pitch 68 half2 = 136 halves)
        {
            half2* stg = (half2*)Ws;
            const int g = lane >> 2, t4 = lane & 3;
#pragma unroll
            for (int mt = 0; mt < 4; mt++)
#pragma unroll
                for (int nt = 0; nt < 4; nt++) {
                    const int row = wm * 64 + mt * 16 + g;
                    const int col = wn * 32 + nt * 8 + t4 * 2;
                    stg[row * 68 + (col >> 1)]       = __floats2half2_rn(acc[mt][nt][0], acc[mt][nt][1]);
                    stg[(row + 8) * 68 + (col >> 1)] = __floats2half2_rn(acc[mt][nt][2], acc[mt][nt][3]);
                }
        }
        __syncthreads();

        // coalesced writeback: 64 halves = 8 uint4 per thread
        {
            const uint4* s4 = reinterpret_cast<const uint4*>(Ws + r * 136 + seg * 64);
            uint4* d4 = reinterpret_cast<uint4*>(g_Ch + (pos0 + r) * 3072 + c * 128 + seg * 64);
#pragma unroll
            for (int i = 0; i < 8; i++) d4[i] = s4[i];
        }
    }
}

// ============================ K2: pointwise ============================
__device__ __forceinline__ void load64(float* dst, const __half* src)
{
    const uint4* s4 = reinterpret_cast<const uint4*>(src);
#pragma unroll
    for (int u = 0; u < 8; u++) {
        uint4 v = s4[u];
        float2 f0 = __half22float2(*reinterpret_cast<half2*>(&v.x));
        float2 f1 = __half22float2(*reinterpret_cast<half2*>(&v.y));
        float2 f2 = __half22float2(*reinterpret_cast<half2*>(&v.z));
        float2 f3 = __half22float2(*reinterpret_cast<half2*>(&v.w));
        dst[u * 8 + 0] = f0.x; dst[u * 8 + 1] = f0.y;
        dst[u * 8 + 2] = f1.x; dst[u * 8 + 3] = f1.y;
        dst[u * 8 + 4] = f2.x; dst[u * 8 + 5] = f2.y;
        dst[u * 8 + 6] = f3.x; dst[u * 8 + 7] = f3.y;
    }
}

__device__ __forceinline__ void lnrot_t(float* x, const float* __restrict__ bias,
                                        const float* __restrict__ g,
                                        const float* __restrict__ b,
                                        const float* __restrict__ ct,
                                        const float* __restrict__ st, int p)
{
    float mu = 0.f;
#pragma unroll
    for (int j = 0; j < 64; j++) { x[j] += bias[j]; mu += x[j]; }
    mu *= (1.f / 64.f);
    float var = 0.f;
#pragma unroll
    for (int j = 0; j < 64; j++) { const float d = x[j] - mu; var += d * d; }
    const float rs = rsqrtf(var * (1.f / 64.f) + EPS_);
#pragma unroll
    for (int j = 0; j < 64; j++) x[j] = (x[j] - mu) * rs * g[j] + b[j];
#pragma unroll
    for (int j = 0; j < 32; j++) {
        const float c = ct[j * 32 + p], s = st[j * 32 + p];
        const float f = x[j], gg = x[j + 32];
        x[j]      = c + (c * f - s * gg);
        x[j + 32] = s + (s * f + c * gg);
    }
}

__global__ void __launch_bounds__(256)
k2_attn(const float* __restrict__ coords,
        const float* __restrict__ biasQ, const float* __restrict__ biasK,
        const float* __restrict__ lnQg, const float* __restrict__ lnQb,
        const float* __restrict__ lnKg, const float* __restrict__ lnKb)
{
    extern __shared__ __align__(16) float sf[];
    float* buf0 = sf;                      // [512][33]
    float* ctab = sf + 512 * 33;           // [2][32 j][32 p]
    float* stab = ctab + 2048;
    const int tid = threadIdx.x, h = tid >> 5, p = tid & 31;
    const size_t pos0 = (size_t)blockIdx.x * 32;
    const size_t gpos = pos0 + p;
    const __half* Cb = g_Ch + gpos * 3072;

    for (int idx = tid; idx < 2048; idx += 256) {
        const int n = idx >> 10, j = (idx >> 5) & 31, pp = idx & 31;
        const float cd = coords[(pos0 + pp) * 2 + n];
        float s, c;
        sincosf(cd * (float)j, &s, &c);
        ctab[idx] = c;
        stab[idx] = s;
    }
    __syncthreads();

    float acc[8];
#pragma unroll
    for (int i = 0; i < 8; i++) acc[i] = 0.f;

#pragma unroll
    for (int n = 0; n < 2; n++) {
        const float* ct = ctab + n * 1024;
        const float* st = stab + n * 1024;
        float kx[64];
        load64(kx, Cb + 1024 + n * 512 + h * 64);
        lnrot_t(kx, biasK + (n * 8 + h) * 64, lnKg + n * 64, lnKb + n * 64, ct, st, p);
        __syncthreads();
#pragma unroll
        for (int j = 0; j < 64; j++) buf0[(h * 64 + j) * 33 + p] = kx[j];
        float qe[64];
        load64(qe, Cb + n * 512 + h * 64);
        lnrot_t(qe, biasQ + (n * 8 + h) * 64, lnQg + n * 64, lnQb + n * 64, ct, st, p);
        __syncthreads();
#pragma unroll
        for (int h2 = 0; h2 < 8; h2++) {
            float a = 0.f;
#pragma unroll
            for (int j = 0; j < 64; j++) a += qe[j] * buf0[(h2 * 64 + j) * 33 + p];
            acc[h2] += a;
        }
    }
    float pr[8], mx = -1e30f, sum = 0.f;
#pragma unroll
    for (int i = 0; i < 8; i++) { acc[i] *= SCALE_; mx = fmaxf(mx, acc[i]); }
#pragma unroll
    for (int i = 0; i < 8; i++) { pr[i] = expf(acc[i] - mx); sum += pr[i]; }
    const float inv = 1.f / sum;
#pragma unroll
    for (int i = 0; i < 8; i++) pr[i] *= inv;

#pragma unroll
    for (int n = 0; n < 2; n++) {
        float vx[64];
        load64(vx, Cb + 2048 + n * 512 + h * 64);
        __syncthreads();
#pragma unroll
        for (int j = 0; j < 64; j++) buf0[(h * 64 + j) * 33 + p] = vx[j];
        __syncthreads();
        float av[64];
#pragma unroll
        for (int j = 0; j < 64; j++) {
            float a = 0.f;
#pragma unroll
            for (int h2 = 0; h2 < 8; h2++) a += pr[h2] * buf0[(h2 * 64 + j) * 33 + p];
            av[j] = a;
        }
        uint4* d4 = reinterpret_cast<uint4*>(g_A2 + gpos * 1024 + h * 128 + n * 64);
#pragma unroll
        for (int u = 0; u < 8; u++) {
            uint4 v;
            half2 h0 = __floats2half2_rn(av[u * 8 + 0], av[u * 8 + 1]);
            half2 h1 = __floats2half2_rn(av[u * 8 + 2], av[u * 8 + 3]);
            half2 h2v = __floats2half2_rn(av[u * 8 + 4], av[u * 8 + 5]);
            half2 h3 = __floats2half2_rn(av[u * 8 + 6], av[u * 8 + 7]);
            v.x = *reinterpret_cast<uint32_t*>(&h0);
            v.y = *reinterpret_cast<uint32_t*>(&h1);
            v.z = *reinterpret_cast<uint32_t*>(&h2v);
            v.w = *reinterpret_cast<uint32_t*>(&h3);
            d4[u] = v;
        }
    }
}

// ============================ K3: output GEMM ============================
// out[pos][c] = A2[pos][1024] * WoT[c][1024]^T + bout.
// CTA = 128 pos x 128 c; warp 64x32 (mt=4, nt=4); smem 69632 -> occ 2.
#define K3_BOFF 34816
#define K3_SMEM 69632

__global__ void __launch_bounds__(256, 2)
k3_out(const float* __restrict__ bout, float* __restrict__ out)
{
    extern __shared__ __align__(16) char sm[];
    __half* As = (__half*)sm;
    __half* Bs = (__half*)(sm + K3_BOFF);
    float*  stage = (float*)sm;              // [128][132] fp32, reuses A+B
    const uint32_t sb = smem_u32(sm);

    const int tid = threadIdx.x, wid = tid >> 5, lane = tid & 31;
    const int wm = wid >> 2, wn = wid & 3;   // warp: rows wm*64, cols wn*32
    const int r = tid >> 1, seg = tid & 1;
    const size_t pos0 = (size_t)(blockIdx.x >> 1) * 128;
    const int c0 = (blockIdx.x & 1) * 128;

    float acc[4][4][4];
#pragma unroll
    for (int mt = 0; mt < 4; mt++)
#pragma unroll
        for (int nt = 0; nt < 4; nt++)
#pragma unroll
            for (int q = 0; q < 4; q++) acc[mt][nt][q] = 0.f;

    for (int kc = 0; kc < 8; kc++) {
        __syncthreads();
        {   // A chunk: 128 rows x 128 k -> 8 uint4 per thread
            const uint4* s4 = reinterpret_cast<const uint4*>(
                g_A2 + (pos0 + r) * 1024 + kc * 128 + seg * 64);
            uint4* d4 = reinterpret_cast<uint4*>(As + r * WP + seg * 64);
#pragma unroll
            for (int i = 0; i < 8; i++) d4[i] = s4[i];
        }
        {   // B chunk: 128 rows x 128 k -> 8 uint4 per thread
            const uint4* s4 = reinterpret_cast<const uint4*>(
                g_WoT + (size_t)(c0 + r) * 1024 + kc * 128 + seg * 64);
            uint4* d4 = reinterpret_cast<uint4*>(Bs + r * WP + seg * 64);
#pragma unroll
            for (int i = 0; i < 8; i++) d4[i] = s4[i];
        }
        __syncthreads();

#pragma unroll
        for (int k0 = 0; k0 < 128; k0 += 32) {
            uint32_t b[4][4];
#pragma unroll
            for (int nt = 0; nt < 4; nt++) {
                const uint32_t bd = sb + K3_BOFF +
                    (((wn * 32 + nt * 8 + (lane & 7)) * WP + k0 + ((lane >> 3) << 3)) << 1);
                LDM_X4(b[nt][0], b[nt][1], b[nt][2], b[nt][3], bd);
            }
#pragma unroll
            for (int half = 0; half < 2; half++) {
                uint32_t a[4][4];
#pragma unroll
                for (int mt = 0; mt < 4; mt++) {
                    const uint32_t ad = sb +
                        (((wm * 64 + mt * 16 + (lane & 15)) * WP
                          + k0 + half * 16 + ((lane >> 4) << 3)) << 1);
                    LDM_X4(a[mt][0], a[mt][1], a[mt][2], a[mt][3], ad);
                }
#pragma unroll
                for (int mt = 0; mt < 4; mt++)
#pragma unroll
                    for (int nt = 0; nt < 4; nt++)
                        MMA16816(acc[mt][nt], a[mt][0], a[mt][1], a[mt][2], a[mt][3],
                                 b[nt][half * 2], b[nt][half * 2 + 1]);
            }
        }
    }
    __syncthreads();
    // stage fp32 result (pitch 132 floats)
    {
        const int g = lane >> 2, t4 = lane & 3;
#pragma unroll
        for (int mt = 0; mt < 4; mt++)
#pragma unroll
            for (int nt = 0; nt < 4; nt++) {
                const int row = wm * 64 + mt * 16 + g;
                const int col = wn * 32 + nt * 8 + t4 * 2;
                stage[row * 132 + col]           = acc[mt][nt][0];
                stage[row * 132 + col + 1]       = acc[mt][nt][1];
                stage[(row + 8) * 132 + col]     = acc[mt][nt][2];
                stage[(row + 8) * 132 + col + 1] = acc[mt][nt][3];
            }
    }
    __syncthreads();
    {
        float* drow = out + (pos0 + r) * 256 + c0 + seg * 64;
        const float* srow = stage + r * 132 + seg * 64;
        const float* brow = bout + c0 + seg * 64;
#pragma unroll
        for (int i = 0; i < 16; i++) {
            float4 v = *reinterpret_cast<const float4*>(srow + i * 4);
            float4 bb = *reinterpret_cast<const float4*>(brow + i * 4);
            v.x += bb.x; v.y += bb.y; v.z += bb.z; v.w += bb.w;
            *reinterpret_cast<float4*>(drow + i * 4) = v;
        }
    }
}

// ---------------------------------------------------------------------------
extern "C" void kernel_launch(void* const* d_in, const int* in_sizes, int n_in,
                              void* d_out, int out_size)
{
    const float* nodal  = (const float*)d_in[0];
    const float* coords = (const float*)d_in[1];
    const float* WQ     = (const float*)d_in[2];
    const float* WK     = (const float*)d_in[3];
    const float* WV     = (const float*)d_in[4];
    const float* biasQ  = (const float*)d_in[5];
    const float* biasK  = (const float*)d_in[6];
    const float* lnQg   = (const float*)d_in[7];
    const float* lnQb   = (const float*)d_in[8];
    const float* lnKg   = (const float*)d_in[9];
    const float* lnKb   = (const float*)d_in[10];
    const float* Wout   = (const float*)d_in[11];
    const float* bout   = (const float*)d_in[12];
    float* out = (float*)d_out;

    cudaFuncSetAttribute(k1_proj, cudaFuncAttributeMaxDynamicSharedMemorySize, K1_SMEM);
    cudaFuncSetAttribute(k2_attn, cudaFuncAttributeMaxDynamicSharedMemorySize, 83968);
    cudaFuncSetAttribute(k3_out,  cudaFuncAttributeMaxDynamicSharedMemorySize, K3_SMEM);

    k0_prep<<<4096, 256>>>(WQ, WK, WV, Wout);
    k1_proj<<<512, 256, K1_SMEM>>>(nodal);
    k2_attn<<<2048, 256, 83968>>>(coords, biasQ, biasK, lnQg, lnQb, lnKg, lnKb);
    k3_out<<<1024, 256, K3_SMEM>>>(bout, out);
}